// round 1
// baseline (speedup 1.0000x reference)
#include <cuda_runtime.h>
#include <math.h>

#define EPSV 1e-5f

// ---------------- scratch (device globals; no allocation allowed) ----------
__device__ float g_xt[1 * 16 * 16 * 1024];        //  1 MB   (C,H,W,B)
__device__ float g_h1[16 * 14 * 14 * 1024];       // 12.8 MB (O,OH,OW,B)
__device__ float g_h2[32 * 12 * 12 * 1024];       // 18.9 MB
__device__ float g_h3[64 * 10 * 10 * 1024];       // 26.2 MB
__device__ float g_stats[224];                    // per-channel sum/sumsq: L1@0(32), L2@32(64), L3@96(128)
__device__ float g_part[25 * 10 * 1024];          // FC partials

// ---------------- zero stats each call (graph replays) ---------------------
__global__ void zero_stats_kernel() {
    int i = threadIdx.x;
    if (i < 224) g_stats[i] = 0.f;
}

// ---------------- transpose x: (B,256) -> (256,B) ---------------------------
__global__ void transpose_kernel(const float* __restrict__ x) {
    __shared__ float tile[32][33];
    int p = blockIdx.x * 32 + threadIdx.x;
    int b = blockIdx.y * 32 + threadIdx.y;
    tile[threadIdx.y][threadIdx.x] = x[b * 256 + p];
    __syncthreads();
    int p2 = blockIdx.x * 32 + threadIdx.y;
    int b2 = blockIdx.y * 32 + threadIdx.x;
    g_xt[p2 * 1024 + b2] = tile[threadIdx.x][threadIdx.y];
}

// ---------------- locally-connected layer + fused BN-stats ------------------
// in : (C, HIN, HIN, 1024)
// W  : (O_TOT, C, OH, OH, 3, 3)
// out: (O_TOT, OH, OH, 1024)
// block: (32, O_BLK/OB); grid: (OH*OH, 1024/(32*MB), O_TOT/O_BLK)
template <int C, int HIN, int OH, int O_BLK, int OB, int MB>
__global__ void __launch_bounds__(32 * (O_BLK / OB))
lc_kernel(const float* __restrict__ in, const float* __restrict__ W,
          const float* __restrict__ bias, float* __restrict__ out,
          float* __restrict__ stats) {
    constexpr int KK  = C * 9;
    constexpr int OGR = O_BLK / OB;
    constexpr int NTH = OGR * 32;

    const int loc    = blockIdx.x;
    const int y      = loc / OH;
    const int x      = loc % OH;
    const int o_base = blockIdx.z * O_BLK;
    const int b0     = blockIdx.y * (32 * MB) + threadIdx.x;
    const int tid    = threadIdx.y * 32 + threadIdx.x;

    __shared__ float Ws[O_BLK * KK];
    __shared__ int   kbase[KK];
    __shared__ float sbias[O_BLK];

    // stage weights for this location
    for (int idx = tid; idx < O_BLK * KK; idx += NTH) {
        int ol = idx / KK, k = idx % KK;
        int c = k / 9, ij = k % 9;
        Ws[idx] = W[((((o_base + ol) * C + c) * OH + y) * OH + x) * 9 + ij];
    }
    for (int k = tid; k < KK; k += NTH) {
        int c = k / 9, ij = k % 9;
        int i = ij / 3, j = ij % 3;
        kbase[k] = ((c * HIN + (y + i)) * HIN + (x + j)) * 1024;
    }
    for (int ol = tid; ol < O_BLK; ol += NTH)
        sbias[ol] = bias[(o_base + ol) * OH * OH + loc];
    __syncthreads();

    float acc[OB][MB];
#pragma unroll
    for (int o = 0; o < OB; o++)
#pragma unroll
        for (int m = 0; m < MB; m++) acc[o][m] = 0.f;

    const float* wp = &Ws[threadIdx.y * OB * KK];
#pragma unroll 2
    for (int k = 0; k < KK; k++) {
        const float* ip = in + kbase[k] + b0;
        float v[MB];
#pragma unroll
        for (int m = 0; m < MB; m++) v[m] = ip[32 * m];
#pragma unroll
        for (int o = 0; o < OB; o++) {
            float w = wp[o * KK + k];
#pragma unroll
            for (int m = 0; m < MB; m++) acc[o][m] = fmaf(v[m], w, acc[o][m]);
        }
    }

    // bias + store + per-channel BN stats (sum, sumsq)
#pragma unroll
    for (int o = 0; o < OB; o++) {
        int og = o_base + threadIdx.y * OB + o;
        float bb = sbias[threadIdx.y * OB + o];
        float* op = out + ((size_t)og * OH * OH + loc) * 1024 + b0;
        float s = 0.f, q = 0.f;
#pragma unroll
        for (int m = 0; m < MB; m++) {
            float r = acc[o][m] + bb;
            op[32 * m] = r;
            s += r;
            q += r * r;
        }
#pragma unroll
        for (int off = 16; off > 0; off >>= 1) {
            s += __shfl_down_sync(0xffffffffu, s, off);
            q += __shfl_down_sync(0xffffffffu, q, off);
        }
        if (threadIdx.x == 0) {
            atomicAdd(&stats[og * 2 + 0], s);
            atomicAdd(&stats[og * 2 + 1], q);
        }
    }
}

// ---------------- BN apply (+ReLU or tanh), in place, float4 ----------------
// grid: (per_chan/1024, O); block 256; per_chan = OH*OH*1024
template <int ACT>  // 0 = relu, 1 = tanh
__global__ void bn_kernel(const float* __restrict__ stats, const float* __restrict__ g,
                          const float* __restrict__ be, float* __restrict__ data,
                          int per_chan) {
    int ch = blockIdx.y;
    float inv  = 1.f / (float)per_chan;
    float mean = stats[ch * 2 + 0] * inv;
    float var  = stats[ch * 2 + 1] * inv - mean * mean;
    float sc   = g[ch] * rsqrtf(var + EPSV);
    float sh   = be[ch] - sc * mean;

    float4* p = (float4*)(data + (size_t)ch * per_chan);
    int i = blockIdx.x * blockDim.x + threadIdx.x;
    float4 v = p[i];
    v.x = sc * v.x + sh; v.y = sc * v.y + sh; v.z = sc * v.z + sh; v.w = sc * v.w + sh;
    if (ACT == 0) {
        v.x = fmaxf(v.x, 0.f); v.y = fmaxf(v.y, 0.f);
        v.z = fmaxf(v.z, 0.f); v.w = fmaxf(v.w, 0.f);
    } else {
        v.x = tanhf(v.x); v.y = tanhf(v.y); v.z = tanhf(v.z); v.w = tanhf(v.w);
    }
    p[i] = v;
}

// ---------------- FC: out[b,t] = sum_f h3[f,b]*fcW[t,f] + fcb[t] ------------
// grid: (4, 25); block 256. Features per chunk = 256, 6400 total.
__global__ void fc_partial_kernel(const float* __restrict__ h, const float* __restrict__ Wfc) {
    const int FCH = 256;
    int b  = blockIdx.x * 256 + threadIdx.x;
    int f0 = blockIdx.y * FCH;
    __shared__ float Wsm[10 * FCH];
    for (int i = threadIdx.x; i < 10 * FCH; i += 256) {
        int t = i / FCH, f = i % FCH;
        Wsm[i] = Wfc[t * 6400 + f0 + f];
    }
    __syncthreads();
    float acc[10];
#pragma unroll
    for (int t = 0; t < 10; t++) acc[t] = 0.f;
    for (int f = 0; f < FCH; f++) {
        float v = h[(size_t)(f0 + f) * 1024 + b];
#pragma unroll
        for (int t = 0; t < 10; t++) acc[t] = fmaf(v, Wsm[t * FCH + f], acc[t]);
    }
#pragma unroll
    for (int t = 0; t < 10; t++)
        g_part[((size_t)blockIdx.y * 10 + t) * 1024 + b] = acc[t];
}

__global__ void fc_reduce_kernel(const float* __restrict__ fcb, float* __restrict__ out) {
    int idx = blockIdx.x * blockDim.x + threadIdx.x;
    if (idx >= 10240) return;
    int b = idx / 10, t = idx % 10;
    float s = fcb[t];
#pragma unroll
    for (int c = 0; c < 25; c++) s += g_part[((size_t)c * 10 + t) * 1024 + b];
    out[b * 10 + t] = s;
}

// ---------------- launch ----------------------------------------------------
extern "C" void kernel_launch(void* const* d_in, const int* in_sizes, int n_in,
                              void* d_out, int out_size) {
    const float* x   = (const float*)d_in[0];
    const float* W1  = (const float*)d_in[1];
    const float* b1  = (const float*)d_in[2];
    const float* g1  = (const float*)d_in[3];
    const float* be1 = (const float*)d_in[4];
    const float* W2  = (const float*)d_in[5];
    const float* b2  = (const float*)d_in[6];
    const float* g2  = (const float*)d_in[7];
    const float* be2 = (const float*)d_in[8];
    const float* W3  = (const float*)d_in[9];
    const float* b3  = (const float*)d_in[10];
    const float* g3  = (const float*)d_in[11];
    const float* be3 = (const float*)d_in[12];
    const float* fcW = (const float*)d_in[13];
    const float* fcb = (const float*)d_in[14];
    float* out = (float*)d_out;

    float *p_xt, *p_h1, *p_h2, *p_h3, *p_stats;
    cudaGetSymbolAddress((void**)&p_xt, g_xt);
    cudaGetSymbolAddress((void**)&p_h1, g_h1);
    cudaGetSymbolAddress((void**)&p_h2, g_h2);
    cudaGetSymbolAddress((void**)&p_h3, g_h3);
    cudaGetSymbolAddress((void**)&p_stats, g_stats);

    zero_stats_kernel<<<1, 256>>>();
    transpose_kernel<<<dim3(8, 32), dim3(32, 32)>>>(x);

    // LC1: C=1,HIN=16,OH=14, O=16 (O_BLK=16, OB=4, MB=8)
    lc_kernel<1, 16, 14, 16, 4, 8><<<dim3(196, 4, 1), dim3(32, 4)>>>(p_xt, W1, b1, p_h1, p_stats + 0);
    bn_kernel<0><<<dim3(196, 16), 256>>>(p_stats + 0, g1, be1, p_h1, 14 * 14 * 1024);

    // LC2: C=16,HIN=14,OH=12, O=32 (O_BLK=32, OB=8, MB=8)
    lc_kernel<16, 14, 12, 32, 8, 8><<<dim3(144, 4, 1), dim3(32, 4)>>>(p_h1, W2, b2, p_h2, p_stats + 32);
    bn_kernel<0><<<dim3(144, 32), 256>>>(p_stats + 32, g2, be2, p_h2, 12 * 12 * 1024);

    // LC3: C=32,HIN=12,OH=10, O=64 split into two 32-channel o-blocks
    lc_kernel<32, 12, 10, 32, 8, 8><<<dim3(100, 4, 2), dim3(32, 4)>>>(p_h2, W3, b3, p_h3, p_stats + 96);
    bn_kernel<1><<<dim3(100, 64), 256>>>(p_stats + 96, g3, be3, p_h3, 10 * 10 * 1024);

    fc_partial_kernel<<<dim3(4, 25), 256>>>(p_h3, fcW);
    fc_reduce_kernel<<<40, 256>>>(fcb, out);
}

// round 2
// speedup vs baseline: 1.0807x; 1.0807x over previous
#include <cuda_runtime.h>
#include <math.h>

#define EPSV 1e-5f

typedef unsigned long long ull;

// ---------------- f32x2 helpers ---------------------------------------------
static __device__ __forceinline__ ull pk2(float lo, float hi) {
    ull r; asm("mov.b64 %0,{%1,%2};" : "=l"(r) : "f"(lo), "f"(hi)); return r;
}
static __device__ __forceinline__ void upk2(ull v, float& lo, float& hi) {
    asm("mov.b64 {%0,%1},%2;" : "=f"(lo), "=f"(hi) : "l"(v));
}
static __device__ __forceinline__ ull f2fma(ull a, ull b, ull c) {
    ull r; asm("fma.rn.f32x2 %0,%1,%2,%3;" : "=l"(r) : "l"(a), "l"(b), "l"(c)); return r;
}
static __device__ __forceinline__ ull f2add(ull a, ull b) {
    ull r; asm("add.rn.f32x2 %0,%1,%2;" : "=l"(r) : "l"(a), "l"(b)); return r;
}

// ---------------- scratch (device globals; no allocation allowed) -----------
__device__ float g_xt[1 * 16 * 16 * 1024];        //  1 MB   (C,H,W,B)
__device__ float g_h1[16 * 14 * 14 * 1024];       // pre-BN LC1 out (O,OH,OW,B)
__device__ float g_h2[32 * 12 * 12 * 1024];       // pre-BN LC2 out
__device__ float g_h3[64 * 10 * 10 * 1024];       // pre-BN LC3 out
__device__ float g_stats[224];                    // sum/sumsq: L1@0(32), L2@32(64), L3@96(128)
__device__ float g_part[25 * 10 * 1024];          // FC partials

// ---------------- zero stats each call (graph replays) ----------------------
__global__ void zero_stats_kernel() {
    int i = threadIdx.x;
    if (i < 224) g_stats[i] = 0.f;
}

// ---------------- transpose x: (B,256) -> (256,B) ----------------------------
__global__ void transpose_kernel(const float* __restrict__ x) {
    __shared__ float tile[32][33];
    int p = blockIdx.x * 32 + threadIdx.x;
    int b = blockIdx.y * 32 + threadIdx.y;
    tile[threadIdx.y][threadIdx.x] = x[b * 256 + p];
    __syncthreads();
    int p2 = blockIdx.x * 32 + threadIdx.y;
    int b2 = blockIdx.y * 32 + threadIdx.x;
    g_xt[p2 * 1024 + b2] = tile[threadIdx.x][threadIdx.y];
}

// ---------------- locally-connected layer, f32x2, fused input-BN+ReLU -------
// in : (C, HIN, HIN, 1024)  pre-BN values of previous layer (or raw x if ACT=0)
// W  : (O_TOT, C, OH, OH, 3, 3);  out: (O_TOT, OH, OH, 1024) pre-BN
// block (32, O_BLK/OB); grid (OH*OH, 4, O_TOT/O_BLK). Each warp: 256 batch, OB outputs.
template <int C, int HIN, int OH, int O_BLK, int OB, int ACT>
__global__ void __launch_bounds__(32 * (O_BLK / OB))
lc_kernel(const float* __restrict__ in, const float* __restrict__ W,
          const float* __restrict__ bias, float* __restrict__ out,
          float* __restrict__ stats_out,
          const float* __restrict__ stats_in, const float* __restrict__ g_in,
          const float* __restrict__ be_in, float inv_n_in) {
    constexpr int KK  = C * 9;
    constexpr int OGR = O_BLK / OB;
    constexpr int NTH = OGR * 32;
    constexpr int MB2 = 4;   // 4 float2 per lane -> 256 batch per warp

    const int loc    = blockIdx.x;
    const int y      = loc / OH;
    const int x      = loc % OH;
    const int o_base = blockIdx.z * O_BLK;
    const int lane   = threadIdx.x;
    const int b0     = blockIdx.y * 256 + lane * 2;
    const int tid    = threadIdx.y * 32 + lane;

    extern __shared__ unsigned char smraw[];
    ull*   Ws2   = (ull*)smraw;                  // duplicated-packed weights
    ull*   s_sc  = Ws2 + O_BLK * KK;
    ull*   s_sh  = s_sc + C;
    float* sbias = (float*)(s_sh + C);
    int*   kbase = (int*)(sbias + O_BLK);

    for (int idx = tid; idx < O_BLK * KK; idx += NTH) {
        int ol = idx / KK, k = idx % KK;
        int c = k / 9, ij = k % 9;
        float w = W[((((o_base + ol) * C + c) * OH + y) * OH + x) * 9 + ij];
        Ws2[idx] = pk2(w, w);
    }
    for (int k = tid; k < KK; k += NTH) {
        int c = k / 9, ij = k % 9;
        int i = ij / 3, j = ij % 3;
        kbase[k] = ((c * HIN + (y + i)) * HIN + (x + j)) * 1024;
    }
    for (int ol = tid; ol < O_BLK; ol += NTH)
        sbias[ol] = bias[(o_base + ol) * OH * OH + loc];
    if (ACT) {
        if (tid < C) {
            float m  = stats_in[tid * 2 + 0] * inv_n_in;
            float v  = stats_in[tid * 2 + 1] * inv_n_in - m * m;
            float sc = g_in[tid] * rsqrtf(v + EPSV);
            float sh = be_in[tid] - sc * m;
            s_sc[tid] = pk2(sc, sc);
            s_sh[tid] = pk2(sh, sh);
        }
    }
    __syncthreads();

    ull acc[OB][MB2];
#pragma unroll
    for (int o = 0; o < OB; o++)
#pragma unroll
        for (int m = 0; m < MB2; m++) acc[o][m] = 0ull;

    const ull* wp = Ws2 + threadIdx.y * OB * KK;

    for (int c = 0; c < C; c++) {
        ull sc2 = 0, sh2 = 0;
        if (ACT) { sc2 = s_sc[c]; sh2 = s_sh[c]; }
#pragma unroll
        for (int ij = 0; ij < 9; ij++) {
            const int k = c * 9 + ij;
            const float* basef = in + kbase[k] + b0;
            ull v[MB2];
#pragma unroll
            for (int m = 0; m < MB2; m++) {
                float2 t = *(const float2*)(basef + 64 * m);
                ull tv = pk2(t.x, t.y);
                if (ACT) {
                    tv = f2fma(tv, sc2, sh2);
                    float lo, hi; upk2(tv, lo, hi);
                    lo = fmaxf(lo, 0.f); hi = fmaxf(hi, 0.f);
                    tv = pk2(lo, hi);
                }
                v[m] = tv;
            }
#pragma unroll
            for (int o = 0; o < OB; o++) {
                ull w2 = wp[o * KK + k];
#pragma unroll
                for (int m = 0; m < MB2; m++) acc[o][m] = f2fma(v[m], w2, acc[o][m]);
            }
        }
    }

    // bias + store pre-BN + per-channel stats (packed sum / sumsq)
#pragma unroll
    for (int o = 0; o < OB; o++) {
        int og = o_base + threadIdx.y * OB + o;
        float bb = sbias[threadIdx.y * OB + o];
        ull b2 = pk2(bb, bb);
        float* op = out + ((size_t)og * OH * OH + loc) * 1024 + b0;
        ull s2 = 0ull, q2 = 0ull;
#pragma unroll
        for (int m = 0; m < MB2; m++) {
            ull r2 = f2add(acc[o][m], b2);
            float lo, hi; upk2(r2, lo, hi);
            *(float2*)(op + 64 * m) = make_float2(lo, hi);
            s2 = f2add(s2, r2);
            q2 = f2fma(r2, r2, q2);
        }
        float sl, sh_, ql, qh;
        upk2(s2, sl, sh_); upk2(q2, ql, qh);
        float s = sl + sh_, q = ql + qh;
#pragma unroll
        for (int off = 16; off > 0; off >>= 1) {
            s += __shfl_down_sync(0xffffffffu, s, off);
            q += __shfl_down_sync(0xffffffffu, q, off);
        }
        if (lane == 0) {
            atomicAdd(&stats_out[og * 2 + 0], s);
            atomicAdd(&stats_out[og * 2 + 1], q);
        }
    }
}

// ---------------- FC with fused BN3 + tanh ----------------------------------
// h3 pre-BN (64,100,1024); feature f = o*100+loc, channel = f/100.
__global__ void fc_partial_kernel(const float* __restrict__ h, const float* __restrict__ Wfc,
                                  const float* __restrict__ stats, const float* __restrict__ g,
                                  const float* __restrict__ be, float inv_n) {
    const int FCH = 256;
    int b  = blockIdx.x * 256 + threadIdx.x;
    int f0 = blockIdx.y * FCH;
    __shared__ float Wsm[10 * FCH];
    __shared__ float s_sc[64], s_sh[64];
    for (int i = threadIdx.x; i < 10 * FCH; i += 256) {
        int t = i / FCH, f = i % FCH;
        Wsm[i] = Wfc[t * 6400 + f0 + f];
    }
    if (threadIdx.x < 64) {
        int ch = threadIdx.x;
        float m  = stats[ch * 2 + 0] * inv_n;
        float v  = stats[ch * 2 + 1] * inv_n - m * m;
        float sc = g[ch] * rsqrtf(v + EPSV);
        s_sc[ch] = sc;
        s_sh[ch] = be[ch] - sc * m;
    }
    __syncthreads();
    float acc[10];
#pragma unroll
    for (int t = 0; t < 10; t++) acc[t] = 0.f;
    for (int f = 0; f < FCH; f++) {
        int fg = f0 + f;
        int ch = fg / 100;
        float v = h[(size_t)fg * 1024 + b];
        v = tanhf(fmaf(v, s_sc[ch], s_sh[ch]));
#pragma unroll
        for (int t = 0; t < 10; t++) acc[t] = fmaf(v, Wsm[t * FCH + f], acc[t]);
    }
#pragma unroll
    for (int t = 0; t < 10; t++)
        g_part[((size_t)blockIdx.y * 10 + t) * 1024 + b] = acc[t];
}

__global__ void fc_reduce_kernel(const float* __restrict__ fcb, float* __restrict__ out) {
    int idx = blockIdx.x * blockDim.x + threadIdx.x;
    if (idx >= 10240) return;
    int b = idx / 10, t = idx % 10;
    float s = fcb[t];
#pragma unroll
    for (int c = 0; c < 25; c++) s += g_part[((size_t)c * 10 + t) * 1024 + b];
    out[b * 10 + t] = s;
}

// ---------------- launch -----------------------------------------------------
static inline int lc_smem(int C, int O_BLK) {
    int KK = C * 9;
    return O_BLK * KK * 8 + C * 16 + O_BLK * 4 + KK * 4;
}

extern "C" void kernel_launch(void* const* d_in, const int* in_sizes, int n_in,
                              void* d_out, int out_size) {
    const float* x   = (const float*)d_in[0];
    const float* W1  = (const float*)d_in[1];
    const float* b1  = (const float*)d_in[2];
    const float* g1  = (const float*)d_in[3];
    const float* be1 = (const float*)d_in[4];
    const float* W2  = (const float*)d_in[5];
    const float* b2  = (const float*)d_in[6];
    const float* g2  = (const float*)d_in[7];
    const float* be2 = (const float*)d_in[8];
    const float* W3  = (const float*)d_in[9];
    const float* b3  = (const float*)d_in[10];
    const float* g3  = (const float*)d_in[11];
    const float* be3 = (const float*)d_in[12];
    const float* fcW = (const float*)d_in[13];
    const float* fcb = (const float*)d_in[14];
    float* out = (float*)d_out;

    float *p_xt, *p_h1, *p_h2, *p_h3, *p_stats;
    cudaGetSymbolAddress((void**)&p_xt, g_xt);
    cudaGetSymbolAddress((void**)&p_h1, g_h1);
    cudaGetSymbolAddress((void**)&p_h2, g_h2);
    cudaGetSymbolAddress((void**)&p_h3, g_h3);
    cudaGetSymbolAddress((void**)&p_stats, g_stats);

    const int sm1 = lc_smem(1, 16);
    const int sm2 = lc_smem(16, 32);
    const int sm3 = lc_smem(32, 32);
    cudaFuncSetAttribute((const void*)lc_kernel<1, 16, 14, 16, 4, 0>,
                         cudaFuncAttributeMaxDynamicSharedMemorySize, sm1);
    cudaFuncSetAttribute((const void*)lc_kernel<16, 14, 12, 32, 8, 1>,
                         cudaFuncAttributeMaxDynamicSharedMemorySize, sm2);
    cudaFuncSetAttribute((const void*)lc_kernel<32, 12, 10, 32, 8, 1>,
                         cudaFuncAttributeMaxDynamicSharedMemorySize, sm3);

    zero_stats_kernel<<<1, 256>>>();
    transpose_kernel<<<dim3(8, 32), dim3(32, 32)>>>(x);

    // LC1: raw input
    lc_kernel<1, 16, 14, 16, 4, 0><<<dim3(196, 4, 1), dim3(32, 4), sm1>>>(
        p_xt, W1, b1, p_h1, p_stats + 0, nullptr, nullptr, nullptr, 0.f);

    // LC2: input = BN1(h1)+ReLU applied inline; n1 = 14*14*1024
    lc_kernel<16, 14, 12, 32, 8, 1><<<dim3(144, 4, 1), dim3(32, 4), sm2>>>(
        p_h1, W2, b2, p_h2, p_stats + 32, p_stats + 0, g1, be1, 1.f / (14.f * 14.f * 1024.f));

    // LC3: input = BN2(h2)+ReLU inline; n2 = 12*12*1024
    lc_kernel<32, 12, 10, 32, 8, 1><<<dim3(100, 4, 2), dim3(32, 4), sm3>>>(
        p_h2, W3, b3, p_h3, p_stats + 96, p_stats + 32, g2, be2, 1.f / (12.f * 12.f * 1024.f));

    // FC: BN3 + tanh fused into loader; n3 = 10*10*1024
    fc_partial_kernel<<<dim3(4, 25), 256>>>(p_h3, fcW, p_stats + 96, g3, be3,
                                            1.f / (10.f * 10.f * 1024.f));
    fc_reduce_kernel<<<40, 256>>>(fcb, out);
}